// round 1
// baseline (speedup 1.0000x reference)
#include <cuda_runtime.h>
#include <math.h>

#define RAD   5
#define Bz    4
#define Ktok  4096
#define Cdim  256
#define Hdim  128
#define NTOK  (Bz*Ktok)           // 16384
#define IBLK  32                  // rows per block in k_weighted

// ---------------- scratch (no allocations allowed) ----------------
__device__ double g_Tpart[Bz*32*Cdim];   // per-chunk double partial col sums
__device__ float  g_T[Bz*Cdim];          // final per-batch column sums
__device__ float  g_e[NTOK];             // exp(s) per token
__device__ float  g_inv[NTOK];           // 1/denom per row

// ---------------- column sums: T[b][c] = sum_j x[b][j][c] ----------------
__global__ void k_colsum(const float* __restrict__ x) {
    int b = blockIdx.y;
    int chunk = blockIdx.x;              // 0..31, 128 rows each
    int c = threadIdx.x;                 // 0..255
    const float* xp = x + ((size_t)b*Ktok + (size_t)chunk*128)*Cdim + c;
    double s = 0.0;
    #pragma unroll 8
    for (int r = 0; r < 128; r++) s += (double)xp[(size_t)r*Cdim];
    g_Tpart[((size_t)b*32 + chunk)*Cdim + c] = s;
}

__global__ void k_reduceT() {
    int b = blockIdx.x;
    int c = threadIdx.x;
    double s = 0.0;
    #pragma unroll
    for (int ch = 0; ch < 32; ch++) s += g_Tpart[((size_t)b*32 + ch)*Cdim + c];
    g_T[b*Cdim + c] = (float)s;
}

// ---------------- MLP: e = exp(tanh(x@W1+b1)@W2 + b2) ----------------
// Tiled fp32 GEMM: BM=64 tokens, BN=128 (full H), BK=16, 256 threads,
// each thread computes a 4x8 microtile. Then fused tanh/W2/exp epilogue.
__global__ void __launch_bounds__(256) k_mlp(const float* __restrict__ x,
                                             const float* __restrict__ W1,
                                             const float* __restrict__ b1,
                                             const float* __restrict__ W2,
                                             const float* __restrict__ b2) {
    __shared__ float As[16][64];    // [kk][token]
    __shared__ float Bs[16][128];   // [kk][hidden]
    __shared__ float sred[64];

    int tid = threadIdx.x;
    int tx = tid & 15;              // hidden group: cols tx*8..tx*8+7
    int ty = tid >> 4;              // token group: rows ty*4..ty*4+3
    int row0 = blockIdx.x * 64;

    float acc[4][8];
    #pragma unroll
    for (int i = 0; i < 4; i++)
        #pragma unroll
        for (int j = 0; j < 8; j++) acc[i][j] = 0.f;

    int t_local = tid >> 2;          // 0..63
    int kq = (tid & 3) << 2;         // 0,4,8,12
    int wk = tid >> 4;               // 0..15
    int wc = (tid & 15) << 3;        // 0..120

    for (int kc = 0; kc < Cdim; kc += 16) {
        __syncthreads();
        float4 xg = *(const float4*)&x[((size_t)(row0 + t_local))*Cdim + kc + kq];
        As[kq+0][t_local] = xg.x;
        As[kq+1][t_local] = xg.y;
        As[kq+2][t_local] = xg.z;
        As[kq+3][t_local] = xg.w;
        float4 wg0 = *(const float4*)&W1[(size_t)(kc + wk)*Hdim + wc];
        float4 wg1 = *(const float4*)&W1[(size_t)(kc + wk)*Hdim + wc + 4];
        *(float4*)&Bs[wk][wc]     = wg0;
        *(float4*)&Bs[wk][wc + 4] = wg1;
        __syncthreads();
        #pragma unroll
        for (int kk = 0; kk < 16; kk++) {
            float4 av  = *(const float4*)&As[kk][ty << 2];
            float4 bv0 = *(const float4*)&Bs[kk][tx << 3];
            float4 bv1 = *(const float4*)&Bs[kk][(tx << 3) + 4];
            float a[4]  = {av.x, av.y, av.z, av.w};
            float bb[8] = {bv0.x, bv0.y, bv0.z, bv0.w, bv1.x, bv1.y, bv1.z, bv1.w};
            #pragma unroll
            for (int i = 0; i < 4; i++)
                #pragma unroll
                for (int j = 0; j < 8; j++) acc[i][j] += a[i] * bb[j];
        }
    }

    // epilogue: h = tanh(acc + b1), partial s = sum_j h*W2[j], reduce over tx
    float part[4] = {0.f, 0.f, 0.f, 0.f};
    #pragma unroll
    for (int j = 0; j < 8; j++) {
        int hn = (tx << 3) + j;
        float b1j = b1[hn];
        float w2j = W2[hn];
        #pragma unroll
        for (int i = 0; i < 4; i++) {
            float h = tanhf(acc[i][j] + b1j);
            part[i] += h * w2j;
        }
    }
    // deterministic reduction across the 16 tx lanes (width-16 shuffle)
    #pragma unroll
    for (int off = 8; off >= 1; off >>= 1) {
        #pragma unroll
        for (int i = 0; i < 4; i++)
            part[i] += __shfl_down_sync(0xffffffffu, part[i], off, 16);
    }
    __syncthreads();
    if (tx == 0) {
        #pragma unroll
        for (int i = 0; i < 4; i++) sred[(ty << 2) + i] = part[i];
    }
    __syncthreads();
    if (tid < 64) {
        g_e[row0 + tid] = expf(sred[tid] + b2[0]);
    }
}

// ---------------- denom: 1 / ((K - nb) + sum_band e) ----------------
__global__ void k_denom() {
    int g = blockIdx.x * 256 + threadIdx.x;   // 0..16383
    int b = g >> 12;
    int i = g & (Ktok - 1);
    int jlo = max(i - RAD, 0), jhi = min(i + RAD, Ktok - 1);
    float s = (float)(Ktok - (jhi - jlo + 1));
    const float* ep = g_e + ((size_t)b << 12);
    for (int j = jlo; j <= jhi; j++) s += ep[j];
    g_inv[g] = 1.0f / s;
}

// ---------------- weights fill: [B,K,K], the 268MB store ----------------
__global__ void __launch_bounds__(256) k_weights(float* __restrict__ wout) {
    __shared__ float bev[16];
    int r = blockIdx.x;                       // 0..16383
    int b = r >> 12, i = r & (Ktok - 1);
    int jlo = max(i - RAD, 0), jhi = min(i + RAD, Ktok - 1);
    int tid = threadIdx.x;
    float inv = g_inv[r];
    if (tid <= jhi - jlo) bev[tid] = g_e[((size_t)b << 12) + jlo + tid] * inv;
    __syncthreads();
    float4 v4 = make_float4(inv, inv, inv, inv);
    float* row = wout + (size_t)r * Ktok;
    int j0 = tid << 4;                        // 16 floats per thread
    #pragma unroll
    for (int q = 0; q < 4; q++) {
        int jj = j0 + (q << 2);
        if (jj + 3 < jlo || jj > jhi) {
            *(float4*)&row[jj] = v4;
        } else {
            float4 t = v4;
            if (jj + 0 >= jlo && jj + 0 <= jhi) t.x = bev[jj + 0 - jlo];
            if (jj + 1 >= jlo && jj + 1 <= jhi) t.y = bev[jj + 1 - jlo];
            if (jj + 2 >= jlo && jj + 2 <= jhi) t.z = bev[jj + 2 - jlo];
            if (jj + 3 >= jlo && jj + 3 <= jhi) t.w = bev[jj + 3 - jlo];
            *(float4*)&row[jj] = t;
        }
    }
}

// ---------------- weighted: (T + sum_band (e-1)x) * inv ----------------
__global__ void __launch_bounds__(256) k_weighted(const float* __restrict__ x,
                                                  float* __restrict__ out) {
    __shared__ float xs[IBLK + 2*RAD][Cdim];   // 42*256*4 = 43008 B
    __shared__ float em1[IBLK + 2*RAD];
    __shared__ float invs[IBLK];

    int blk = blockIdx.x;                  // 0..511
    int b = blk >> 7;                      // 128 blocks per batch
    int i0 = (blk & 127) << 5;             // row base within batch
    int jlo = max(i0 - RAD, 0);
    int jhi = min(i0 + IBLK - 1 + RAD, Ktok - 1);
    int n = jhi - jlo + 1;                 // <= 42
    int tid = threadIdx.x;

    const float* xb = x + (((size_t)b << 12) + jlo) * Cdim;
    for (int idx = tid; idx < n * Cdim; idx += 256)
        xs[idx >> 8][idx & 255] = xb[idx];
    if (tid < n)    em1[tid]  = g_e[((size_t)b << 12) + jlo + tid] - 1.0f;
    if (tid < IBLK) invs[tid] = g_inv[((size_t)b << 12) + i0 + tid];
    float Tc = g_T[b * Cdim + tid];
    __syncthreads();

    int c = tid;
    float* op = out + (((size_t)b << 12) + i0) * Cdim + c;
    for (int ii = 0; ii < IBLK; ii++) {
        int i = i0 + ii;
        int lo = max(i - RAD, 0) - jlo;
        int hi = min(i + RAD, Ktok - 1) - jlo;
        float acc = Tc;
        for (int r = lo; r <= hi; r++) acc += em1[r] * xs[r][c];
        op[(size_t)ii * Cdim] = acc * invs[ii];
    }
}

// ---------------- launch ----------------
extern "C" void kernel_launch(void* const* d_in, const int* in_sizes, int n_in,
                              void* d_out, int out_size) {
    (void)in_sizes; (void)n_in; (void)out_size;
    const float* x  = (const float*)d_in[0];
    const float* W1 = (const float*)d_in[1];
    const float* b1 = (const float*)d_in[2];
    const float* W2 = (const float*)d_in[3];
    const float* b2 = (const float*)d_in[4];

    float* out_weighted = (float*)d_out;                          // [B,K,C]
    float* out_weights  = (float*)d_out + (size_t)NTOK * Cdim;    // [B,K,K]

    k_colsum  <<<dim3(32, Bz), 256>>>(x);
    k_mlp     <<<NTOK / 64,    256>>>(x, W1, b1, W2, b2);
    k_reduceT <<<Bz,           256>>>();
    k_denom   <<<NTOK / 256,   256>>>();
    k_weights <<<NTOK,         256>>>(out_weights);
    k_weighted<<<NTOK / IBLK,  256>>>(x, out_weighted);
}

// round 2
// speedup vs baseline: 1.1973x; 1.1973x over previous
#include <cuda_runtime.h>
#include <math.h>

#define RAD   5
#define Bz    4
#define Ktok  4096
#define Cdim  256
#define Hdim  128
#define NTOK  (Bz*Ktok)           // 16384
#define IBLK  16                  // rows per weighted block
#define NWBLK (NTOK/IBLK)         // 1024 weighted blocks

// ---------------- scratch ----------------
__device__ float  g_Tpart[256*Cdim];     // per-mlp-block (64-token chunk) col sums
__device__ float  g_T[Bz*Cdim];          // final per-batch column sums
__device__ float  g_e[NTOK];             // exp(s) per token
__device__ float  g_inv[NTOK];           // 1/denom per row

// ---------------- MLP + fused column-sum partials ----------------
// Tile 64 tokens x 128 hidden, BK=16, 256 threads, 4x8 microtile.
__global__ void __launch_bounds__(256) k_mlp(const float* __restrict__ x,
                                             const float* __restrict__ W1,
                                             const float* __restrict__ b1,
                                             const float* __restrict__ W2,
                                             const float* __restrict__ b2) {
    __shared__ float As[16][64];    // [kk][token]
    __shared__ float Bs[16][128];   // [kk][hidden]
    __shared__ float sred[64];

    int tid = threadIdx.x;
    int tx = tid & 15;              // hidden group: cols tx*8..tx*8+7
    int ty = tid >> 4;              // token group: rows ty*4..ty*4+3
    int row0 = blockIdx.x * 64;

    float acc[4][8];
    #pragma unroll
    for (int i = 0; i < 4; i++)
        #pragma unroll
        for (int j = 0; j < 8; j++) acc[i][j] = 0.f;

    int t_local = tid >> 2;          // 0..63
    int kq = (tid & 3) << 2;         // 0,4,8,12
    int wk = tid >> 4;               // 0..15
    int wc = (tid & 15) << 3;        // 0..120

    // colsum mapping: c_local = tid>>4 (0..15), g = tid&15 sums tokens 4g..4g+3
    int cs_c = tid >> 4;
    int cs_g = tid & 15;

    for (int kc = 0; kc < Cdim; kc += 16) {
        __syncthreads();
        float4 xg = *(const float4*)&x[((size_t)(row0 + t_local))*Cdim + kc + kq];
        As[kq+0][t_local] = xg.x;
        As[kq+1][t_local] = xg.y;
        As[kq+2][t_local] = xg.z;
        As[kq+3][t_local] = xg.w;
        float4 wg0 = *(const float4*)&W1[(size_t)(kc + wk)*Hdim + wc];
        float4 wg1 = *(const float4*)&W1[(size_t)(kc + wk)*Hdim + wc + 4];
        *(float4*)&Bs[wk][wc]     = wg0;
        *(float4*)&Bs[wk][wc + 4] = wg1;
        __syncthreads();

        // fused column-sum partial for c = kc + cs_c over this block's 64 tokens
        {
            float4 cv = *(const float4*)&As[cs_c][cs_g << 2];
            float cs = (cv.x + cv.y) + (cv.z + cv.w);
            #pragma unroll
            for (int off = 8; off >= 1; off >>= 1)
                cs += __shfl_down_sync(0xffffffffu, cs, off, 16);
            if (cs_g == 0)
                g_Tpart[(size_t)blockIdx.x * Cdim + kc + cs_c] = cs;
        }

        #pragma unroll
        for (int kk = 0; kk < 16; kk++) {
            float4 av  = *(const float4*)&As[kk][ty << 2];
            float4 bv0 = *(const float4*)&Bs[kk][tx << 3];
            float4 bv1 = *(const float4*)&Bs[kk][(tx << 3) + 4];
            float a[4]  = {av.x, av.y, av.z, av.w};
            float bb[8] = {bv0.x, bv0.y, bv0.z, bv0.w, bv1.x, bv1.y, bv1.z, bv1.w};
            #pragma unroll
            for (int i = 0; i < 4; i++)
                #pragma unroll
                for (int j = 0; j < 8; j++) acc[i][j] += a[i] * bb[j];
        }
    }

    // epilogue: h = tanh(acc + b1), s = sum_h h*W2[h], deterministic reduce
    float part[4] = {0.f, 0.f, 0.f, 0.f};
    #pragma unroll
    for (int j = 0; j < 8; j++) {
        int hn = (tx << 3) + j;
        float b1j = b1[hn];
        float w2j = W2[hn];
        #pragma unroll
        for (int i = 0; i < 4; i++) {
            float h = tanhf(acc[i][j] + b1j);
            part[i] += h * w2j;
        }
    }
    #pragma unroll
    for (int off = 8; off >= 1; off >>= 1) {
        #pragma unroll
        for (int i = 0; i < 4; i++)
            part[i] += __shfl_down_sync(0xffffffffu, part[i], off, 16);
    }
    __syncthreads();
    if (tx == 0) {
        #pragma unroll
        for (int i = 0; i < 4; i++) sred[(ty << 2) + i] = part[i];
    }
    __syncthreads();
    if (tid < 64) {
        g_e[row0 + tid] = expf(sred[tid] + b2[0]);
    }
}

// ---------------- mid: reduce T + compute 1/denom ----------------
// grid 68 blocks: bid<4 -> T reduce (one batch each); bid>=4 -> denom rows
__global__ void __launch_bounds__(256) k_mid() {
    int bid = blockIdx.x;
    int tid = threadIdx.x;
    if (bid < 4) {
        int b = bid, c = tid;
        double s = 0.0;
        #pragma unroll
        for (int ch = 0; ch < 64; ch++)
            s += (double)g_Tpart[(size_t)(b*64 + ch)*Cdim + c];
        g_T[b*Cdim + c] = (float)s;
    } else {
        int g = (bid - 4) * 256 + tid;        // 0..16383
        int b = g >> 12;
        int i = g & (Ktok - 1);
        int jlo = max(i - RAD, 0), jhi = min(i + RAD, Ktok - 1);
        float s = (float)(Ktok - (jhi - jlo + 1));
        const float* ep = g_e + ((size_t)b << 12);
        #pragma unroll
        for (int j = 0; j < 2*RAD + 1; j++) {
            int jj = jlo + j;
            if (jj <= jhi) s += ep[jj];
        }
        g_inv[g] = 1.0f / s;
    }
}

// ---------------- fused output: weighted blocks first, then weights rows ----
__global__ void __launch_bounds__(256) k_fused(const float* __restrict__ x,
                                               float* __restrict__ wout,
                                               float* __restrict__ outw) {
    __shared__ float xs[(IBLK + 2*RAD) * Cdim];   // 26*256*4 = 26624 B
    __shared__ float em1[32];
    __shared__ float invs[IBLK];

    int bid = blockIdx.x;
    int tid = threadIdx.x;

    if (bid >= NWBLK) {
        // ---- weights row fill: the 268MB store ----
        int r = bid - NWBLK;                      // 0..16383
        int b = r >> 12, i = r & (Ktok - 1);
        int jlo = max(i - RAD, 0), jhi = min(i + RAD, Ktok - 1);
        float inv = g_inv[r];
        if (tid <= jhi - jlo) em1[tid] = g_e[((size_t)b << 12) + jlo + tid] * inv;
        __syncthreads();
        float4 v4 = make_float4(inv, inv, inv, inv);
        float* row = wout + (size_t)r * Ktok;
        int j0 = tid << 4;                        // 16 floats per thread
        #pragma unroll
        for (int q = 0; q < 4; q++) {
            int jj = j0 + (q << 2);
            float4 t = v4;
            if (!(jj + 3 < jlo || jj > jhi)) {
                if (jj + 0 >= jlo && jj + 0 <= jhi) t.x = em1[jj + 0 - jlo];
                if (jj + 1 >= jlo && jj + 1 <= jhi) t.y = em1[jj + 1 - jlo];
                if (jj + 2 >= jlo && jj + 2 <= jhi) t.z = em1[jj + 2 - jlo];
                if (jj + 3 >= jlo && jj + 3 <= jhi) t.w = em1[jj + 3 - jlo];
            }
            __stcs((float4*)&row[jj], t);
        }
    } else {
        // ---- weighted: out[i,:] = (T + sum_band (e_j-1) x_j) * inv_i ----
        int b = bid >> 8;                         // 256 blocks per batch
        int i0 = (bid & 255) << 4;                // row base within batch
        int jlo = max(i0 - RAD, 0);
        int jhi = min(i0 + IBLK - 1 + RAD, Ktok - 1);
        int n = jhi - jlo + 1;                    // <= 26

        const float* xb = x + (((size_t)b << 12) + jlo) * Cdim;
        for (int idx = tid; idx < n * Cdim; idx += 256)
            xs[idx] = xb[idx];
        if (tid < n)    em1[tid]  = g_e[((size_t)b << 12) + jlo + tid] - 1.0f;
        if (tid < IBLK) invs[tid] = g_inv[((size_t)b << 12) + i0 + tid];
        float Tc = g_T[b * Cdim + tid];
        __syncthreads();

        int c = tid;
        float* op = outw + (((size_t)b << 12) + i0) * Cdim + c;
        #pragma unroll
        for (int ii = 0; ii < IBLK; ii++) {
            int i = i0 + ii;
            int lo = max(i - RAD, 0) - jlo;
            int hi = min(i + RAD, Ktok - 1) - jlo;
            float acc = Tc;
            for (int r = lo; r <= hi; r++) acc += em1[r] * xs[r * Cdim + c];
            __stcs(&op[(size_t)ii * Cdim], acc * invs[ii]);
        }
    }
}

// ---------------- launch ----------------
extern "C" void kernel_launch(void* const* d_in, const int* in_sizes, int n_in,
                              void* d_out, int out_size) {
    (void)in_sizes; (void)n_in; (void)out_size;
    const float* x  = (const float*)d_in[0];
    const float* W1 = (const float*)d_in[1];
    const float* b1 = (const float*)d_in[2];
    const float* W2 = (const float*)d_in[3];
    const float* b2 = (const float*)d_in[4];

    float* out_weighted = (float*)d_out;                          // [B,K,C]
    float* out_weights  = (float*)d_out + (size_t)NTOK * Cdim;    // [B,K,K]

    k_mlp  <<<NTOK / 64,      256>>>(x, W1, b1, W2, b2);
    k_mid  <<<4 + NTOK / 256, 256>>>();
    k_fused<<<NWBLK + NTOK,   256>>>(x, out_weights, out_weighted);
}

// round 3
// speedup vs baseline: 1.7689x; 1.4774x over previous
#include <cuda_runtime.h>
#include <math.h>

#define RAD   5
#define Bz    4
#define Ktok  4096
#define Cdim  256
#define Hdim  128
#define NTOK  (Bz*Ktok)           // 16384
#define IBLK  16                  // rows per weighted block
#define NWBLK (NTOK/IBLK)         // 1024 weighted blocks
#define WROWS 8                   // rows per weights block
#define NWTBLK (NTOK/WROWS)       // 2048 weights blocks

// ---------------- scratch ----------------
__device__ float  g_Tpart[256*Cdim];     // per-mlp-block (64-token chunk) col sums
__device__ float  g_T[Bz*Cdim];          // final per-batch column sums
__device__ float  g_e[NTOK];             // exp(s) per token
__device__ float  g_inv[NTOK];           // 1/denom per row

// ---------------- MLP (8x8 microtile) + fused column-sum partials ----------
// BM=64 tokens, BN=128 (full H), BK=16, 128 threads, each thread 8x8.
#define ASP 68   // padded As row stride (floats)
__global__ void __launch_bounds__(128, 4) k_mlp(const float* __restrict__ x,
                                                const float* __restrict__ W1,
                                                const float* __restrict__ b1,
                                                const float* __restrict__ W2,
                                                const float* __restrict__ b2) {
    __shared__ float As[16*ASP];     // [kk][token(64) pad 68]
    __shared__ float Bs[16*128];     // [kk][hidden]
    __shared__ float sred[64];

    int tid = threadIdx.x;
    int tx = tid & 15;               // hidden group: cols tx*8..tx*8+7
    int ty = tid >> 4;               // token group: rows ty*8..ty*8+7
    int row0 = blockIdx.x * 64;

    float acc[8][8];
    #pragma unroll
    for (int i = 0; i < 8; i++)
        #pragma unroll
        for (int j = 0; j < 8; j++) acc[i][j] = 0.f;

    for (int kc = 0; kc < Cdim; kc += 16) {
        __syncthreads();
        // fill As: 64 tokens x 16 k = 256 float4, 2 per thread
        #pragma unroll
        for (int q = 0; q < 2; q++) {
            int idx = q * 128 + tid;             // 0..255
            int token = idx >> 2;
            int kq = (idx & 3) << 2;
            float4 xg = *(const float4*)&x[(size_t)(row0 + token)*Cdim + kc + kq];
            As[(kq+0)*ASP + token] = xg.x;
            As[(kq+1)*ASP + token] = xg.y;
            As[(kq+2)*ASP + token] = xg.z;
            As[(kq+3)*ASP + token] = xg.w;
        }
        // fill Bs: 16 k x 128 hidden = 512 float4, 4 per thread
        #pragma unroll
        for (int q = 0; q < 4; q++) {
            int idx = q * 128 + tid;             // 0..511
            int wk = idx >> 5;
            int wc = (idx & 31) << 2;
            *(float4*)&Bs[wk*128 + wc] = *(const float4*)&W1[(size_t)(kc + wk)*Hdim + wc];
        }
        __syncthreads();

        // fused column-sum partials: c = kc + (tid>>3), 8 lanes sum 8 tokens each
        {
            int cs_c = tid >> 3;                 // 0..15
            int cs_g = tid & 7;                  // 0..7
            float4 a0 = *(const float4*)&As[cs_c*ASP + (cs_g << 3)];
            float4 a1 = *(const float4*)&As[cs_c*ASP + (cs_g << 3) + 4];
            float cs = ((a0.x+a0.y)+(a0.z+a0.w)) + ((a1.x+a1.y)+(a1.z+a1.w));
            #pragma unroll
            for (int off = 4; off >= 1; off >>= 1)
                cs += __shfl_down_sync(0xffffffffu, cs, off, 8);
            if (cs_g == 0)
                g_Tpart[(size_t)blockIdx.x * Cdim + kc + cs_c] = cs;
        }

        #pragma unroll
        for (int kk = 0; kk < 16; kk++) {
            float4 a0 = *(const float4*)&As[kk*ASP + (ty << 3)];
            float4 a1 = *(const float4*)&As[kk*ASP + (ty << 3) + 4];
            float4 b0 = *(const float4*)&Bs[kk*128 + (tx << 3)];
            float4 b1v = *(const float4*)&Bs[kk*128 + (tx << 3) + 4];
            float a[8]  = {a0.x, a0.y, a0.z, a0.w, a1.x, a1.y, a1.z, a1.w};
            float bb[8] = {b0.x, b0.y, b0.z, b0.w, b1v.x, b1v.y, b1v.z, b1v.w};
            #pragma unroll
            for (int i = 0; i < 8; i++)
                #pragma unroll
                for (int j = 0; j < 8; j++) acc[i][j] += a[i] * bb[j];
        }
    }

    // epilogue: h = tanh(acc + b1), s = sum_h h*W2[h], deterministic reduce
    float part[8] = {0.f,0.f,0.f,0.f,0.f,0.f,0.f,0.f};
    #pragma unroll
    for (int j = 0; j < 8; j++) {
        int hn = (tx << 3) + j;
        float b1j = b1[hn];
        float w2j = W2[hn];
        #pragma unroll
        for (int i = 0; i < 8; i++)
            part[i] += tanhf(acc[i][j] + b1j) * w2j;
    }
    #pragma unroll
    for (int off = 8; off >= 1; off >>= 1) {
        #pragma unroll
        for (int i = 0; i < 8; i++)
            part[i] += __shfl_down_sync(0xffffffffu, part[i], off, 16);
    }
    __syncthreads();
    if (tx == 0) {
        #pragma unroll
        for (int i = 0; i < 8; i++) sred[(ty << 3) + i] = part[i];
    }
    __syncthreads();
    if (tid < 64) {
        g_e[row0 + tid] = expf(sred[tid] + b2[0]);
    }
}

// ---------------- mid: reduce T + compute 1/denom ----------------
__global__ void __launch_bounds__(256) k_mid() {
    int bid = blockIdx.x;
    int tid = threadIdx.x;
    if (bid < 4) {
        int b = bid, c = tid;
        double s = 0.0;
        #pragma unroll
        for (int ch = 0; ch < 64; ch++)
            s += (double)g_Tpart[(size_t)(b*64 + ch)*Cdim + c];
        g_T[b*Cdim + c] = (float)s;
    } else {
        int g = (bid - 4) * 256 + tid;        // 0..16383
        int b = g >> 12;
        int i = g & (Ktok - 1);
        int jlo = max(i - RAD, 0), jhi = min(i + RAD, Ktok - 1);
        float s = (float)(Ktok - (jhi - jlo + 1));
        const float* ep = g_e + ((size_t)b << 12);
        #pragma unroll
        for (int j = 0; j < 2*RAD + 1; j++) {
            int jj = jlo + j;
            if (jj <= jhi) s += ep[jj];
        }
        g_inv[g] = 1.0f / s;
    }
}

// ---------------- fused output: weighted + weights interleaved 1:2 --------
__global__ void __launch_bounds__(256) k_fused(const float* __restrict__ x,
                                               float* __restrict__ wout,
                                               float* __restrict__ outw) {
    __shared__ float xs[(IBLK + 2*RAD) * Cdim];   // 26*256*4 = 26624 B (reused)
    __shared__ float em1[32];
    __shared__ float invs[IBLK];

    int bid = blockIdx.x;              // 0..3071
    int tid = threadIdx.x;
    int g3 = bid % 3;
    int q  = bid / 3;                  // 0..1023

    if (g3 != 0) {
        // ---- weights fill: 8 rows per block, 128KB streamed store ----
        int chunk = q * 2 + (g3 - 1);             // 0..2047
        int r0 = chunk * WROWS;
        int b = r0 >> 12, i0 = r0 & (Ktok - 1);
        int jlo0 = max(i0 - RAD, 0);
        int jhi0 = min(i0 + WROWS - 1 + RAD, Ktok - 1);
        int n = jhi0 - jlo0 + 1;                  // <= 18
        float* sev  = xs;                          // reuse smem
        float* sinv = xs + 32;
        if (tid < n)     sev[tid]  = g_e[((size_t)b << 12) + jlo0 + tid];
        if (tid < WROWS) sinv[tid] = g_inv[r0 + tid];
        __syncthreads();

        #pragma unroll
        for (int ii = 0; ii < WROWS; ii++) {
            int i = i0 + ii;
            float inv = sinv[ii];
            int jlo = max(i - RAD, 0), jhi = min(i + RAD, Ktok - 1);
            float* row = wout + (size_t)(r0 + ii) * Ktok;
            float4 v4 = make_float4(inv, inv, inv, inv);
            #pragma unroll
            for (int q2 = 0; q2 < 4; q2++) {
                int jj = (q2 << 10) + (tid << 2);
                float4 t = v4;
                if (jj + 3 >= jlo && jj <= jhi) {
                    if (jj + 0 >= jlo && jj + 0 <= jhi) t.x = sev[jj + 0 - jlo0] * inv;
                    if (jj + 1 >= jlo && jj + 1 <= jhi) t.y = sev[jj + 1 - jlo0] * inv;
                    if (jj + 2 >= jlo && jj + 2 <= jhi) t.z = sev[jj + 2 - jlo0] * inv;
                    if (jj + 3 >= jlo && jj + 3 <= jhi) t.w = sev[jj + 3 - jlo0] * inv;
                }
                __stcs((float4*)&row[jj], t);
            }
        }
    } else {
        // ---- weighted: out[i,:] = (T + sum_band (e_j-1) x_j) * inv_i ----
        int b = q >> 8;                           // 256 blocks per batch
        int i0 = (q & 255) << 4;                  // row base within batch
        int jlo = max(i0 - RAD, 0);
        int jhi = min(i0 + IBLK - 1 + RAD, Ktok - 1);
        int n = jhi - jlo + 1;                    // <= 26

        const float* xb = x + (((size_t)b << 12) + jlo) * Cdim;
        for (int idx = tid; idx < n * Cdim; idx += 256)
            xs[idx] = xb[idx];
        if (tid < n)    em1[tid]  = g_e[((size_t)b << 12) + jlo + tid] - 1.0f;
        if (tid < IBLK) invs[tid] = g_inv[((size_t)b << 12) + i0 + tid];
        float Tc = g_T[b * Cdim + tid];
        __syncthreads();

        int c = tid;
        float* op = outw + (((size_t)b << 12) + i0) * Cdim + c;
        #pragma unroll
        for (int ii = 0; ii < IBLK; ii++) {
            int i = i0 + ii;
            int lo = max(i - RAD, 0) - jlo;
            int hi = min(i + RAD, Ktok - 1) - jlo;
            float acc = Tc;
            for (int r = lo; r <= hi; r++) acc += em1[r] * xs[r * Cdim + c];
            __stcs(&op[(size_t)ii * Cdim], acc * invs[ii]);
        }
    }
}

// ---------------- launch ----------------
extern "C" void kernel_launch(void* const* d_in, const int* in_sizes, int n_in,
                              void* d_out, int out_size) {
    (void)in_sizes; (void)n_in; (void)out_size;
    const float* x  = (const float*)d_in[0];
    const float* W1 = (const float*)d_in[1];
    const float* b1 = (const float*)d_in[2];
    const float* W2 = (const float*)d_in[3];
    const float* b2 = (const float*)d_in[4];

    float* out_weighted = (float*)d_out;                          // [B,K,C]
    float* out_weights  = (float*)d_out + (size_t)NTOK * Cdim;    // [B,K,K]

    k_mlp  <<<NTOK / 64,       128>>>(x, W1, b1, W2, b2);
    k_mid  <<<4 + NTOK / 256,  256>>>();
    k_fused<<<NWBLK + NWTBLK,  256>>>(x, out_weights, out_weighted);
}